// round 3
// baseline (speedup 1.0000x reference)
#include <cuda_runtime.h>
#include <stdint.h>

// BurgerDissipativeLossOperator — sector-optimized segment-mean formulation.
//
// du[i]  = (u1[i]*A[i] - B[i]) / max(cnt[i],1),  A=Σ 1/len, B=Σ u1[src]/len over in-edges
// d2u[i] = (du[i]*A[i] - C[i]) / max(cnt[i],1),  C=Σ du[src]/len
// loss   = ((u0-u1)/dt + du*u1 - MU*d2u) * mask
//
// Accumulators packed as float4 {A, B, cnt, C} so all atomics for a node hit
// one 32B L2 sector.

#define N_NODES 4000000
#define N_EDGES 8000000
#define INV_DT  100.0f
#define MU      0.01f

__device__ float4 g_acc[N_NODES];   // {A, B, cnt, C}
__device__ float  g_du[N_NODES];

// ---------------------------------------------------------------------------
__global__ void k_zero() {
    int i = blockIdx.x * blockDim.x + threadIdx.x;
    if (i < N_NODES) {
        g_acc[i] = make_float4(0.f, 0.f, 0.f, 0.f);
    }
}

// edge pass 1: A[d]+=1/len ; B[d]+=u1[s]/len ; cnt[d]+=1
__global__ void k_edge1(const int* __restrict__ ei,
                        const float* __restrict__ x_t1,
                        const float* __restrict__ attr) {
    int e = blockIdx.x * blockDim.x + threadIdx.x;
    if (e >= N_EDGES) return;
    int s = ei[e];
    int d = ei[N_EDGES + e];
    float r  = 1.0f / attr[e];
    float us = __ldg(&x_t1[2 * s]);
    float* p = &g_acc[d].x;
    atomicAdd(p + 0, r);        // A
    atomicAdd(p + 1, us * r);   // B
    atomicAdd(p + 2, 1.0f);     // cnt
}

// node pass: du = (u1*A - B) / max(cnt,1)
__global__ void k_du(const float* __restrict__ x_t1) {
    int i = blockIdx.x * blockDim.x + threadIdx.x;
    if (i < N_NODES) {
        float4 a = g_acc[i];
        float u1 = x_t1[2 * i];
        float c  = fmaxf(a.z, 1.0f);
        g_du[i]  = (u1 * a.x - a.y) / c;
    }
}

// edge pass 2: C[d] += du[s]/len
__global__ void k_edge2(const int* __restrict__ ei,
                        const float* __restrict__ attr) {
    int e = blockIdx.x * blockDim.x + threadIdx.x;
    if (e >= N_EDGES) return;
    int s = ei[e];
    int d = ei[N_EDGES + e];
    float r = 1.0f / attr[e];
    float ds = __ldg(&g_du[s]);
    atomicAdd(&g_acc[d].w, ds * r);   // C
}

// epilogue: d2u = (du*A - C)/max(cnt,1); loss = ((u0-u1)/dt + du*u1 - MU*d2u)*mask
__global__ void k_final(const float* __restrict__ x_t,
                        const float* __restrict__ x_t1,
                        const float* __restrict__ mask,
                        float* __restrict__ out) {
    int i = blockIdx.x * blockDim.x + threadIdx.x;
    if (i < N_NODES) {
        float4 a = g_acc[i];
        float du = g_du[i];
        float c  = fmaxf(a.z, 1.0f);
        float d2u = (du * a.x - a.w) / c;
        float u0 = x_t[2 * i];
        float u1 = x_t1[2 * i];
        float loss = (u0 - u1) * INV_DT + du * u1 - MU * d2u;
        out[i] = loss * mask[i];
    }
}

// ---------------------------------------------------------------------------
extern "C" void kernel_launch(void* const* d_in, const int* in_sizes, int n_in,
                              void* d_out, int out_size) {
    const float* x_t  = (const float*)d_in[0];
    const float* x_t1 = (const float*)d_in[1];
    const int*   ei   = (const int*)d_in[2];
    const float* attr = (const float*)d_in[3];
    const float* mask = (const float*)d_in[4];
    float*       out  = (float*)d_out;

    const int TB = 256;
    const int gn = (N_NODES + TB - 1) / TB;
    const int ge = (N_EDGES + TB - 1) / TB;

    k_zero <<<gn, TB>>>();
    k_edge1<<<ge, TB>>>(ei, x_t1, attr);
    k_du   <<<gn, TB>>>(x_t1);
    k_edge2<<<ge, TB>>>(ei, attr);
    k_final<<<gn, TB>>>(x_t, x_t1, mask, out);
}

// round 4
// speedup vs baseline: 1.3048x; 1.3048x over previous
#include <cuda_runtime.h>
#include <stdint.h>

// BurgerDissipativeLossOperator
//   du[i]  = (u1[i]*A[i] - B[i]) / max(cnt[i],1)   A=Σ 1/len, B=Σ u1[src]/len
//   d2u[i] = (du[i]*A[i] - C[i]) / max(cnt[i],1)   C=Σ du[src]/len
//   loss   = ((u0-u1)/dt + du*u1 - MU*d2u) * mask
//
// Pass 1 accumulates {A,B,cnt} with a single red.global.add.v4.f32 per edge
// (one LTS transaction). Pass 2 accumulates C in a compact 16MB array so
// randomly-touched data stays L2-resident.

#define N_NODES 4000000
#define N_EDGES 8000000
#define INV_DT  100.0f
#define MU      0.01f

__device__ float4 g_acc[N_NODES];   // {A, B, cnt, pad}
__device__ float  g_C[N_NODES];     // Σ du[src]/len
__device__ float  g_du[N_NODES];
__device__ float  g_u1[N_NODES];    // compacted x_t1[:,0]

// ---------------------------------------------------------------------------
// init: zero accumulators, compact u1
__global__ void k_init(const float* __restrict__ x_t1) {
    int i = blockIdx.x * blockDim.x + threadIdx.x;
    if (i < N_NODES) {
        g_acc[i] = make_float4(0.f, 0.f, 0.f, 0.f);
        g_C[i]   = 0.f;
        g_u1[i]  = x_t1[2 * i];
    }
}

// pass 1: single v4 reduction per edge: {A += 1/len, B += u1[s]/len, cnt += 1}
__global__ void k_edge1(const int* __restrict__ ei,
                        const float* __restrict__ attr) {
    int e = blockIdx.x * blockDim.x + threadIdx.x;
    if (e >= N_EDGES) return;
    int s = ei[e];
    int d = ei[N_EDGES + e];
    float r  = 1.0f / attr[e];
    float us = __ldg(&g_u1[s]);
    float4* p = &g_acc[d];
    asm volatile("red.global.add.v4.f32 [%0], {%1, %2, %3, %4};"
                 :: "l"(p), "f"(r), "f"(us * r), "f"(1.0f), "f"(0.0f)
                 : "memory");
}

// node pass: du = (u1*A - B) / max(cnt,1)
__global__ void k_du() {
    int i = blockIdx.x * blockDim.x + threadIdx.x;
    if (i < N_NODES) {
        float4 a = g_acc[i];
        float c  = fmaxf(a.z, 1.0f);
        g_du[i]  = (g_u1[i] * a.x - a.y) / c;
    }
}

// pass 2: C[d] += du[s]/len
__global__ void k_edge2(const int* __restrict__ ei,
                        const float* __restrict__ attr) {
    int e = blockIdx.x * blockDim.x + threadIdx.x;
    if (e >= N_EDGES) return;
    int s = ei[e];
    int d = ei[N_EDGES + e];
    float r  = 1.0f / attr[e];
    float ds = __ldg(&g_du[s]);
    atomicAdd(&g_C[d], ds * r);
}

// epilogue: d2u = (du*A - C)/max(cnt,1); loss = ((u0-u1)/dt + du*u1 - MU*d2u)*mask
__global__ void k_final(const float* __restrict__ x_t,
                        const float* __restrict__ mask,
                        float* __restrict__ out) {
    int i = blockIdx.x * blockDim.x + threadIdx.x;
    if (i < N_NODES) {
        float4 a  = g_acc[i];
        float du  = g_du[i];
        float c   = fmaxf(a.z, 1.0f);
        float d2u = (du * a.x - g_C[i]) / c;
        float u0  = x_t[2 * i];
        float u1  = g_u1[i];
        float loss = (u0 - u1) * INV_DT + du * u1 - MU * d2u;
        out[i] = loss * mask[i];
    }
}

// ---------------------------------------------------------------------------
extern "C" void kernel_launch(void* const* d_in, const int* in_sizes, int n_in,
                              void* d_out, int out_size) {
    const float* x_t  = (const float*)d_in[0];
    const float* x_t1 = (const float*)d_in[1];
    const int*   ei   = (const int*)d_in[2];
    const float* attr = (const float*)d_in[3];
    const float* mask = (const float*)d_in[4];
    float*       out  = (float*)d_out;

    const int TB = 256;
    const int gn = (N_NODES + TB - 1) / TB;
    const int ge = (N_EDGES + TB - 1) / TB;

    k_init <<<gn, TB>>>(x_t1);
    k_edge1<<<ge, TB>>>(ei, attr);
    k_du   <<<gn, TB>>>();
    k_edge2<<<ge, TB>>>(ei, attr);
    k_final<<<gn, TB>>>(x_t, mask, out);
}

// round 5
// speedup vs baseline: 1.4234x; 1.0909x over previous
#include <cuda_runtime.h>
#include <stdint.h>

// BurgerDissipativeLossOperator
//   du[i]  = (u1[i]*A[i] - B[i]) / max(cnt[i],1)   A=Σ 1/len, B=Σ u1[src]/len
//   d2u[i] = (du[i]*A[i] - C[i]) / max(cnt[i],1)   C=Σ du[src]/len
//   loss   = ((u0-u1)/dt + du*u1 - MU*d2u) * mask
//
// Edge pass 1: one red.global.add.v4.f32 per edge for {A,B,cnt}.
// Edge pass 2: one scalar red per edge into compact g_C.
// All edge-stream loads use __ldcs (evict-first) to keep the randomly
// accessed node arrays L2-resident. 4 edges / 4 nodes per thread.

#define N_NODES 4000000
#define N_EDGES 8000000
#define INV_DT  100.0f
#define MU      0.01f

__device__ float4 g_acc[N_NODES];   // {A, B, cnt, pad}
__device__ float  g_C[N_NODES];     // Σ du[src]/len
__device__ float  g_du[N_NODES];
__device__ float  g_u1[N_NODES];    // compacted x_t1[:,0]

// ---------------------------------------------------------------------------
// init (4 nodes/thread): zero accumulators, compact u1
__global__ void k_init(const float4* __restrict__ x_t1) {
    int t = blockIdx.x * blockDim.x + threadIdx.x;   // node group
    if (t >= N_NODES / 4) return;
    int i = t * 4;
    float4 z = make_float4(0.f, 0.f, 0.f, 0.f);
    g_acc[i + 0] = z;
    g_acc[i + 1] = z;
    g_acc[i + 2] = z;
    g_acc[i + 3] = z;
    ((float4*)g_C)[t] = z;
    // x_t1 is (N,2): nodes i..i+3 live in x_t1 float4 elements [t*2], [t*2+1]
    float4 a = __ldcs(&x_t1[t * 2 + 0]);   // u1[i], v, u1[i+1], v
    float4 b = __ldcs(&x_t1[t * 2 + 1]);   // u1[i+2], v, u1[i+3], v
    ((float4*)g_u1)[t] = make_float4(a.x, a.z, b.x, b.z);
}

// pass 1 (4 edges/thread): red.v4 {A += 1/len, B += u1[s]/len, cnt += 1}
__global__ void k_edge1(const int4* __restrict__ ei_s,
                        const int4* __restrict__ ei_d,
                        const float4* __restrict__ attr) {
    int t = blockIdx.x * blockDim.x + threadIdx.x;
    if (t >= N_EDGES / 4) return;
    int4   s4 = __ldcs(&ei_s[t]);
    int4   d4 = __ldcs(&ei_d[t]);
    float4 l4 = __ldcs(&attr[t]);

    float u0 = __ldg(&g_u1[s4.x]);
    float u1 = __ldg(&g_u1[s4.y]);
    float u2 = __ldg(&g_u1[s4.z]);
    float u3 = __ldg(&g_u1[s4.w]);

    float r0 = 1.0f / l4.x, r1 = 1.0f / l4.y, r2 = 1.0f / l4.z, r3 = 1.0f / l4.w;

    asm volatile("red.global.add.v4.f32 [%0], {%1, %2, %3, %4};"
                 :: "l"(&g_acc[d4.x]), "f"(r0), "f"(u0 * r0), "f"(1.0f), "f"(0.0f) : "memory");
    asm volatile("red.global.add.v4.f32 [%0], {%1, %2, %3, %4};"
                 :: "l"(&g_acc[d4.y]), "f"(r1), "f"(u1 * r1), "f"(1.0f), "f"(0.0f) : "memory");
    asm volatile("red.global.add.v4.f32 [%0], {%1, %2, %3, %4};"
                 :: "l"(&g_acc[d4.z]), "f"(r2), "f"(u2 * r2), "f"(1.0f), "f"(0.0f) : "memory");
    asm volatile("red.global.add.v4.f32 [%0], {%1, %2, %3, %4};"
                 :: "l"(&g_acc[d4.w]), "f"(r3), "f"(u3 * r3), "f"(1.0f), "f"(0.0f) : "memory");
}

// node pass (4 nodes/thread): du = (u1*A - B) / max(cnt,1)
__global__ void k_du() {
    int t = blockIdx.x * blockDim.x + threadIdx.x;
    if (t >= N_NODES / 4) return;
    int i = t * 4;
    float4 u = ((const float4*)g_u1)[t];
    float4 a0 = g_acc[i + 0];
    float4 a1 = g_acc[i + 1];
    float4 a2 = g_acc[i + 2];
    float4 a3 = g_acc[i + 3];
    float4 du;
    du.x = (u.x * a0.x - a0.y) / fmaxf(a0.z, 1.0f);
    du.y = (u.y * a1.x - a1.y) / fmaxf(a1.z, 1.0f);
    du.z = (u.z * a2.x - a2.y) / fmaxf(a2.z, 1.0f);
    du.w = (u.w * a3.x - a3.y) / fmaxf(a3.z, 1.0f);
    ((float4*)g_du)[t] = du;
}

// pass 2 (4 edges/thread): C[d] += du[s]/len
__global__ void k_edge2(const int4* __restrict__ ei_s,
                        const int4* __restrict__ ei_d,
                        const float4* __restrict__ attr) {
    int t = blockIdx.x * blockDim.x + threadIdx.x;
    if (t >= N_EDGES / 4) return;
    int4   s4 = __ldcs(&ei_s[t]);
    int4   d4 = __ldcs(&ei_d[t]);
    float4 l4 = __ldcs(&attr[t]);

    float d0 = __ldg(&g_du[s4.x]);
    float d1 = __ldg(&g_du[s4.y]);
    float d2 = __ldg(&g_du[s4.z]);
    float d3 = __ldg(&g_du[s4.w]);

    atomicAdd(&g_C[d4.x], d0 / l4.x);
    atomicAdd(&g_C[d4.y], d1 / l4.y);
    atomicAdd(&g_C[d4.z], d2 / l4.z);
    atomicAdd(&g_C[d4.w], d3 / l4.w);
}

// epilogue (4 nodes/thread)
__global__ void k_final(const float4* __restrict__ x_t,
                        const float4* __restrict__ mask,
                        float4* __restrict__ out) {
    int t = blockIdx.x * blockDim.x + threadIdx.x;
    if (t >= N_NODES / 4) return;
    int i = t * 4;
    float4 a0 = g_acc[i + 0];
    float4 a1 = g_acc[i + 1];
    float4 a2 = g_acc[i + 2];
    float4 a3 = g_acc[i + 3];
    float4 du = ((const float4*)g_du)[t];
    float4 C  = ((const float4*)g_C)[t];
    float4 u1 = ((const float4*)g_u1)[t];
    float4 xa = __ldcs(&x_t[t * 2 + 0]);
    float4 xb = __ldcs(&x_t[t * 2 + 1]);
    float4 m  = __ldcs(&mask[t]);

    float4 o;
    o.x = ((xa.x - u1.x) * INV_DT + du.x * u1.x - MU * (du.x * a0.x - C.x) / fmaxf(a0.z, 1.0f)) * m.x;
    o.y = ((xa.z - u1.y) * INV_DT + du.y * u1.y - MU * (du.y * a1.x - C.y) / fmaxf(a1.z, 1.0f)) * m.y;
    o.z = ((xb.x - u1.z) * INV_DT + du.z * u1.z - MU * (du.z * a2.x - C.z) / fmaxf(a2.z, 1.0f)) * m.z;
    o.w = ((xb.z - u1.w) * INV_DT + du.w * u1.w - MU * (du.w * a3.x - C.w) / fmaxf(a3.z, 1.0f)) * m.w;
    out[t] = o;
}

// ---------------------------------------------------------------------------
extern "C" void kernel_launch(void* const* d_in, const int* in_sizes, int n_in,
                              void* d_out, int out_size) {
    const float4* x_t  = (const float4*)d_in[0];
    const float4* x_t1 = (const float4*)d_in[1];
    const int*    ei   = (const int*)d_in[2];
    const float4* attr = (const float4*)d_in[3];
    const float4* mask = (const float4*)d_in[4];
    float4*       out  = (float4*)d_out;

    const int4* ei_s = (const int4*)ei;
    const int4* ei_d = (const int4*)(ei + N_EDGES);

    const int TB = 256;
    const int gn = (N_NODES / 4 + TB - 1) / TB;
    const int ge = (N_EDGES / 4 + TB - 1) / TB;

    k_init <<<gn, TB>>>(x_t1);
    k_edge1<<<ge, TB>>>(ei_s, ei_d, attr);
    k_du   <<<gn, TB>>>();
    k_edge2<<<ge, TB>>>(ei_s, ei_d, attr);
    k_final<<<gn, TB>>>(x_t, mask, out);
}

// round 6
// speedup vs baseline: 1.6766x; 1.1779x over previous
#include <cuda_runtime.h>
#include <stdint.h>

// BurgerDissipativeLossOperator
//   du[i]  = (u1[i]*A[i] - B[i]) / max(cnt[i],1)   A=Σ 1/len, B=Σ u1[src]/len
//   d2u[i] = (du[i]*A[i] - C[i]) / max(cnt[i],1)   C=Σ du[src]/len
//   loss   = ((u0-u1)/dt + du*u1 - MU*d2u) * mask
//
// Packing trick: V = Σ (256 + 1/len) = 256*cnt + A  (A ≤ 2*cnt << 256),
// so pass 1 needs only a red.global.add.v2.f32 {V, B} -> 8B accumulator.
// All randomly-accessed arrays total 80MB < 126MB L2; edge streams use
// __ldcs so they stay resident.

#define N_NODES 4000000
#define N_EDGES 8000000
#define INV_DT  100.0f
#define MU      0.01f
#define K_PACK  256.0f
#define INV_K   0.00390625f   // 1/256

__device__ float2 g_acc[N_NODES];   // {V = 256*cnt + A, B}
__device__ float  g_C[N_NODES];     // Σ du[src]/len
__device__ float  g_du[N_NODES];
__device__ float  g_u1[N_NODES];    // compacted x_t1[:,0]

// ---------------------------------------------------------------------------
// init (4 nodes/thread): zero accumulators, compact u1
__global__ void k_init(const float4* __restrict__ x_t1) {
    int t = blockIdx.x * blockDim.x + threadIdx.x;
    if (t >= N_NODES / 4) return;
    float4 z = make_float4(0.f, 0.f, 0.f, 0.f);
    ((float4*)g_acc)[t * 2 + 0] = z;   // nodes 4t,4t+1
    ((float4*)g_acc)[t * 2 + 1] = z;   // nodes 4t+2,4t+3
    ((float4*)g_C)[t] = z;
    float4 a = __ldcs(&x_t1[t * 2 + 0]);
    float4 b = __ldcs(&x_t1[t * 2 + 1]);
    ((float4*)g_u1)[t] = make_float4(a.x, a.z, b.x, b.z);
}

// pass 1 (4 edges/thread): red.v2 {V += 256 + 1/len, B += u1[s]/len}
__global__ void k_edge1(const int4* __restrict__ ei_s,
                        const int4* __restrict__ ei_d,
                        const float4* __restrict__ attr) {
    int t = blockIdx.x * blockDim.x + threadIdx.x;
    if (t >= N_EDGES / 4) return;
    int4   s4 = __ldcs(&ei_s[t]);
    int4   d4 = __ldcs(&ei_d[t]);
    float4 l4 = __ldcs(&attr[t]);

    float u0 = __ldg(&g_u1[s4.x]);
    float u1 = __ldg(&g_u1[s4.y]);
    float u2 = __ldg(&g_u1[s4.z]);
    float u3 = __ldg(&g_u1[s4.w]);

    float r0 = 1.0f / l4.x, r1 = 1.0f / l4.y, r2 = 1.0f / l4.z, r3 = 1.0f / l4.w;

    asm volatile("red.global.add.v2.f32 [%0], {%1, %2};"
                 :: "l"(&g_acc[d4.x]), "f"(K_PACK + r0), "f"(u0 * r0) : "memory");
    asm volatile("red.global.add.v2.f32 [%0], {%1, %2};"
                 :: "l"(&g_acc[d4.y]), "f"(K_PACK + r1), "f"(u1 * r1) : "memory");
    asm volatile("red.global.add.v2.f32 [%0], {%1, %2};"
                 :: "l"(&g_acc[d4.z]), "f"(K_PACK + r2), "f"(u2 * r2) : "memory");
    asm volatile("red.global.add.v2.f32 [%0], {%1, %2};"
                 :: "l"(&g_acc[d4.w]), "f"(K_PACK + r3), "f"(u3 * r3) : "memory");
}

// node pass (4 nodes/thread): unpack cnt/A, du = (u1*A - B) / max(cnt,1)
__device__ __forceinline__ float node_du(float V, float B, float u1) {
    float k = floorf(V * INV_K);          // cnt
    float A = V - K_PACK * k;
    float c = fmaxf(k, 1.0f);
    return (u1 * A - B) / c;
}

__global__ void k_du() {
    int t = blockIdx.x * blockDim.x + threadIdx.x;
    if (t >= N_NODES / 4) return;
    float4 u  = ((const float4*)g_u1)[t];
    float4 p0 = ((const float4*)g_acc)[t * 2 + 0];  // {V0,B0,V1,B1}
    float4 p1 = ((const float4*)g_acc)[t * 2 + 1];  // {V2,B2,V3,B3}
    float4 du;
    du.x = node_du(p0.x, p0.y, u.x);
    du.y = node_du(p0.z, p0.w, u.y);
    du.z = node_du(p1.x, p1.y, u.z);
    du.w = node_du(p1.z, p1.w, u.w);
    ((float4*)g_du)[t] = du;
}

// pass 2 (4 edges/thread): C[d] += du[s]/len
__global__ void k_edge2(const int4* __restrict__ ei_s,
                        const int4* __restrict__ ei_d,
                        const float4* __restrict__ attr) {
    int t = blockIdx.x * blockDim.x + threadIdx.x;
    if (t >= N_EDGES / 4) return;
    int4   s4 = __ldcs(&ei_s[t]);
    int4   d4 = __ldcs(&ei_d[t]);
    float4 l4 = __ldcs(&attr[t]);

    float d0 = __ldg(&g_du[s4.x]);
    float d1 = __ldg(&g_du[s4.y]);
    float d2 = __ldg(&g_du[s4.z]);
    float d3 = __ldg(&g_du[s4.w]);

    atomicAdd(&g_C[d4.x], d0 / l4.x);
    atomicAdd(&g_C[d4.y], d1 / l4.y);
    atomicAdd(&g_C[d4.z], d2 / l4.z);
    atomicAdd(&g_C[d4.w], d3 / l4.w);
}

// epilogue (4 nodes/thread)
__device__ __forceinline__ float node_loss(float V, float C, float du,
                                           float u0, float u1, float m) {
    float k = floorf(V * INV_K);
    float A = V - K_PACK * k;
    float c = fmaxf(k, 1.0f);
    float d2u = (du * A - C) / c;
    return ((u0 - u1) * INV_DT + du * u1 - MU * d2u) * m;
}

__global__ void k_final(const float4* __restrict__ x_t,
                        const float4* __restrict__ mask,
                        float4* __restrict__ out) {
    int t = blockIdx.x * blockDim.x + threadIdx.x;
    if (t >= N_NODES / 4) return;
    float4 p0 = ((const float4*)g_acc)[t * 2 + 0];
    float4 p1 = ((const float4*)g_acc)[t * 2 + 1];
    float4 du = ((const float4*)g_du)[t];
    float4 C  = ((const float4*)g_C)[t];
    float4 u1 = ((const float4*)g_u1)[t];
    float4 xa = __ldcs(&x_t[t * 2 + 0]);
    float4 xb = __ldcs(&x_t[t * 2 + 1]);
    float4 m  = __ldcs(&mask[t]);

    float4 o;
    o.x = node_loss(p0.x, C.x, du.x, xa.x, u1.x, m.x);
    o.y = node_loss(p0.z, C.y, du.y, xa.z, u1.y, m.y);
    o.z = node_loss(p1.x, C.z, du.z, xb.x, u1.z, m.z);
    o.w = node_loss(p1.z, C.w, du.w, xb.z, u1.w, m.w);
    out[t] = o;
}

// ---------------------------------------------------------------------------
extern "C" void kernel_launch(void* const* d_in, const int* in_sizes, int n_in,
                              void* d_out, int out_size) {
    const float4* x_t  = (const float4*)d_in[0];
    const float4* x_t1 = (const float4*)d_in[1];
    const int*    ei   = (const int*)d_in[2];
    const float4* attr = (const float4*)d_in[3];
    const float4* mask = (const float4*)d_in[4];
    float4*       out  = (float4*)d_out;

    const int4* ei_s = (const int4*)ei;
    const int4* ei_d = (const int4*)(ei + N_EDGES);

    const int TB = 256;
    const int gn = (N_NODES / 4 + TB - 1) / TB;
    const int ge = (N_EDGES / 4 + TB - 1) / TB;

    k_init <<<gn, TB>>>(x_t1);
    k_edge1<<<ge, TB>>>(ei_s, ei_d, attr);
    k_du   <<<gn, TB>>>();
    k_edge2<<<ge, TB>>>(ei_s, ei_d, attr);
    k_final<<<gn, TB>>>(x_t, mask, out);
}